// round 2
// baseline (speedup 1.0000x reference)
#include <cuda_runtime.h>
#include <cuda_bf16.h>

// x: (1,128,56,56) f32   d_in[0]
// W: (64,16,3)     f32   d_in[1]
// out: (1,32,56,56) f32
//
// y[g,k,n,m] = sum_{i<64,j<3} W[i,k,j] * t_pad[g*64+i, n, m+j]
//   t_pad[c,n,s]: s==0||s==57 -> 0; else x[c,n,(s+54)%56]   (fused roll+pad)
// out[g*16+k, (n+1)%56, m] = y[g,k,n,m]                      (fused output roll)

#define C_IN 64      // input channels per group
#define K_OUT 16     // output channels per group
#define HW 56
#define XS_STRIDE 58 // 56 cols + 2 halo, padded row stride

__global__ __launch_bounds__(128, 1)
void shifted_gconv_kernel(const float* __restrict__ x,
                          const float* __restrict__ W,
                          float* __restrict__ out)
{
    const int n = blockIdx.x;   // conv row 0..55
    const int g = blockIdx.y;   // group 0..1
    const int tid = threadIdx.x;

    __shared__ float xs[C_IN * XS_STRIDE];   // 64 x 58 = 14848 B
    __shared__ float ws[C_IN * K_OUT * 3];   // 3072 floats = 12288 B

    // ---- stage W (shared across groups), coalesced ----
    #pragma unroll
    for (int idx = tid; idx < C_IN * K_OUT * 3; idx += 128)
        ws[idx] = W[idx];

    // ---- stage x slab for this (g, n): fused roll(+1) + pad ----
    // xs[i][s] = t_pad[g*64+i, n, s];  x col w maps to s = (w+2<=56)? w+2 : w-54
    const float* xrow = x + (size_t)g * C_IN * HW * HW + (size_t)n * HW;
    for (int idx = tid; idx < C_IN * HW; idx += 128) {
        const int i = idx / HW;
        const int w = idx - i * HW;
        const int s = (w + 2 <= 56) ? (w + 2) : (w - 54);
        xs[i * XS_STRIDE + s] = xrow[(size_t)i * HW * HW + w];
    }
    // zero the pad columns (s = 0 and s = 57)
    for (int i = tid; i < C_IN; i += 128) {
        xs[i * XS_STRIDE + 0]  = 0.f;
        xs[i * XS_STRIDE + 57] = 0.f;
    }
    __syncthreads();

    // ---- compute: thread = (k, m-octant); each thread does 7 consecutive m ----
    const int k  = tid >> 3;         // 0..15
    const int mg = tid & 7;          // 0..7
    const int m0 = mg * 7;           // 0,7,...,49

    float acc[7];
    #pragma unroll
    for (int q = 0; q < 7; q++) acc[q] = 0.f;

    const float* wp = ws + k * 3;    // ws[i*48 + k*3 + j]

    #pragma unroll 4
    for (int i = 0; i < C_IN; i++) {
        const float* xr = xs + i * XS_STRIDE + m0;
        float v[9];
        #pragma unroll
        for (int q = 0; q < 9; q++) v[q] = xr[q];

        const float w0 = wp[i * 48 + 0];
        const float w1 = wp[i * 48 + 1];
        const float w2 = wp[i * 48 + 2];

        #pragma unroll
        for (int q = 0; q < 7; q++)
            acc[q] = fmaf(w0, v[q], fmaf(w1, v[q + 1], fmaf(w2, v[q + 2], acc[q])));
    }

    // ---- store with fused output roll along H: row n -> row (n+1)%56 ----
    const int nh = (n + 1 == HW) ? 0 : n + 1;
    float* orow = out + ((size_t)(g * K_OUT + k) * HW + nh) * HW + m0;
    #pragma unroll
    for (int q = 0; q < 7; q++) orow[q] = acc[q];
}

extern "C" void kernel_launch(void* const* d_in, const int* in_sizes, int n_in,
                              void* d_out, int out_size)
{
    const float* x = (const float*)d_in[0];
    const float* W = (const float*)d_in[1];
    float* out = (float*)d_out;

    dim3 grid(HW, 2);   // 56 rows x 2 groups = 112 blocks
    shifted_gconv_kernel<<<grid, 128>>>(x, W, out);
}

// round 6
// speedup vs baseline: 1.1801x; 1.1801x over previous
#include <cuda_runtime.h>
#include <cuda_bf16.h>

// x: (1,128,56,56) f32   d_in[0]
// W: (64,16,3)     f32   d_in[1]
// out: (1,32,56,56) f32
//
// y[g,k,n,m] = sum_{i<64,j<3} W[i,k,j] * t_pad[g*64+i, n, m+j]
//   t_pad[c,n,s]: s==0||s==57 -> 0; else x[c,n,(s+54)%56]   (fused roll+pad)
// out[g*16+k, (n+1)%56, m] = y[g,k,n,m]                      (fused output roll)

#define C_IN 64
#define K_OUT 16
#define HW 56
#define XS_STRIDE 58
#define NSPLIT 4          // channel-split factor
#define I_PER (C_IN / NSPLIT)   // 16 channels per split
#define NTHREADS 512

__global__ __launch_bounds__(NTHREADS, 1)
void shifted_gconv_kernel(const float* __restrict__ x,
                          const float* __restrict__ W,
                          float* __restrict__ out)
{
    const int n = blockIdx.x;   // conv row 0..55
    const int g = blockIdx.y;   // group 0..1
    const int tid = threadIdx.x;

    __shared__ float xs[C_IN * XS_STRIDE];        // 14848 B
    __shared__ float ws[C_IN * K_OUT * 3];        // 12288 B
    __shared__ float red[NSPLIT][128 * 7];        // 14336 B

    // ---- stage W, coalesced ----
    #pragma unroll
    for (int idx = tid; idx < C_IN * K_OUT * 3; idx += NTHREADS)
        ws[idx] = W[idx];

    // ---- stage x slab for this (g, n): fused roll(+1) + pad ----
    const float* xrow = x + (size_t)g * C_IN * HW * HW + (size_t)n * HW;
    #pragma unroll
    for (int idx = tid; idx < C_IN * HW; idx += NTHREADS) {
        const int i = idx / HW;
        const int w = idx - i * HW;
        const int s = (w + 2 <= 56) ? (w + 2) : (w - 54);
        xs[i * XS_STRIDE + s] = xrow[(size_t)i * HW * HW + w];
    }
    // zero pad columns (s = 0 and s = 57)
    for (int i = tid; i < C_IN; i += NTHREADS) {
        xs[i * XS_STRIDE + 0]  = 0.f;
        xs[i * XS_STRIDE + 57] = 0.f;
    }
    __syncthreads();

    // ---- compute: thread = (isplit, k, m-octant); 7 consecutive m each ----
    const int isplit = tid >> 7;        // 0..3
    const int r  = tid & 127;           // 0..127
    const int k  = r >> 3;              // 0..15
    const int mg = r & 7;               // 0..7
    const int m0 = mg * 7;

    float acc[7];
    #pragma unroll
    for (int q = 0; q < 7; q++) acc[q] = 0.f;

    const float* wp = ws + k * 3;
    const int ibase = isplit * I_PER;

    #pragma unroll 4
    for (int ii = 0; ii < I_PER; ii++) {
        const int i = ibase + ii;
        const float* xr = xs + i * XS_STRIDE + m0;
        float v[9];
        #pragma unroll
        for (int q = 0; q < 9; q++) v[q] = xr[q];

        const float w0 = wp[i * 48 + 0];
        const float w1 = wp[i * 48 + 1];
        const float w2 = wp[i * 48 + 2];

        #pragma unroll
        for (int q = 0; q < 7; q++)
            acc[q] = fmaf(w0, v[q], fmaf(w1, v[q + 1], fmaf(w2, v[q + 2], acc[q])));
    }

    // ---- cross-split reduction in smem (stride-7 layout: conflict-free) ----
    #pragma unroll
    for (int q = 0; q < 7; q++)
        red[isplit][r * 7 + q] = acc[q];
    __syncthreads();

    if (tid < 128) {
        float fin[7];
        #pragma unroll
        for (int q = 0; q < 7; q++)
            fin[q] = red[0][tid * 7 + q] + red[1][tid * 7 + q]
                   + red[2][tid * 7 + q] + red[3][tid * 7 + q];

        // store with fused output roll along H: row n -> row (n+1)%56
        const int nh = (n + 1 == HW) ? 0 : n + 1;
        const int kk = tid >> 3;
        const int mm0 = (tid & 7) * 7;
        float* orow = out + ((size_t)(g * K_OUT + kk) * HW + nh) * HW + mm0;
        #pragma unroll
        for (int q = 0; q < 7; q++) orow[q] = fin[q];
    }
}

extern "C" void kernel_launch(void* const* d_in, const int* in_sizes, int n_in,
                              void* d_out, int out_size)
{
    const float* x = (const float*)d_in[0];
    const float* W = (const float*)d_in[1];
    float* out = (float*)d_out;

    dim3 grid(HW, 2);   // 56 rows x 2 groups = 112 blocks
    shifted_gconv_kernel<<<grid, NTHREADS>>>(x, W, out);
}